// round 8
// baseline (speedup 1.0000x reference)
#include <cuda_runtime.h>
#include <cuda_fp16.h>
#include <math.h>
#include <stdint.h>

#define NMAX   50000
#define EMAX   1600000
#define DIM    32
#define DATTR  16
#define NRBF   8
#define NBINS  1024
#define LMAX   8.0f
#define RCUT   5.0f
#define SCALEC 1.0f

// ---------------- static device scratch ----------------
__device__ float   g_xattr[NMAX * DATTR];
__device__ float   g_h    [NMAX * DIM];
__device__ __half2 g_hmh  [NMAX * (DIM / 2)];   // hm rows in fp16 (64B/node)
__device__ float   g_agg  [NMAX * DIM];
__device__ __half2 g_Th   [3 * NBINS * DIM];    // packed (T[b], T[b+1]) endpoints
// CSR
__device__ int     g_off  [NMAX + 1];
__device__ int     g_cur  [NMAX];
__device__ float4  g_meta [EMAX];               // {src bits, u, half2(ux,uy) bits, uz}

static __device__ __forceinline__ float siluf(float v) {
    return v / (1.0f + __expf(-v));
}

// ---------------------------------------------------------------------------
// rw(len) for one table row (whole warp participates).
// ---------------------------------------------------------------------------
static __device__ __forceinline__ float eval_rw(const float* __restrict__ Wr1,
                                                const float* __restrict__ br1,
                                                const float* __restrict__ Wr2,
                                                int i, int b, int lane) {
    const float len   = (float)b * (LMAX / (float)(NBINS - 1));
    const float gamma = (NRBF / RCUT) * (NRBF / RCUT);

    float r = 0.0f;
    if (lane < NRBF) {
        float c = (float)lane * (RCUT / (float)(NRBF - 1));
        float d = len - c;
        r = expf(-gamma * d * d);
    }
    float t = br1[i * DIM + lane];
#pragma unroll
    for (int j = 0; j < NRBF; j++) {
        float rj = __shfl_sync(0xffffffffu, r, j);
        t += rj * Wr1[(i * NRBF + j) * DIM + lane];
    }
    t = fmaxf(t, 0.0f);

    float acc = 0.0f;
#pragma unroll
    for (int k = 0; k < DIM; k++) {
        float tk = __shfl_sync(0xffffffffu, t, k);
        acc += tk * Wr2[(i * DIM + k) * DIM + lane];
    }
    return acc;
}

__global__ void k_table(const float* __restrict__ Wr1,
                        const float* __restrict__ br1,
                        const float* __restrict__ Wr2) {
    int w    = (blockIdx.x * blockDim.x + threadIdx.x) >> 5;
    int lane = threadIdx.x & 31;
    if (w >= 3 * NBINS) return;
    int i = w / NBINS;
    int b = w - i * NBINS;
    int b1 = (b + 1 < NBINS) ? b + 1 : b;

    float a0 = eval_rw(Wr1, br1, Wr2, i, b,  lane);
    float a1 = eval_rw(Wr1, br1, Wr2, i, b1, lane);
    g_Th[(i * NBINS + b) * DIM + lane] = __floats2half2_rn(a0, a1);
}

// ---------------------------------------------------------------------------
// CSR build
// ---------------------------------------------------------------------------
__global__ void k_hist4(const int* __restrict__ ei, int E) {
    int e4 = (blockIdx.x * blockDim.x + threadIdx.x) * 4;
    if (e4 + 3 < E) {
        int4 v = *(const int4*)(ei + E + e4);
        atomicAdd(&g_cur[v.x], 1);
        atomicAdd(&g_cur[v.y], 1);
        atomicAdd(&g_cur[v.z], 1);
        atomicAdd(&g_cur[v.w], 1);
    } else {
        for (int e = e4; e < E; e++) atomicAdd(&g_cur[ei[E + e]], 1);
    }
}

__global__ void k_hist1(const int* __restrict__ ei, int E) {
    int e = blockIdx.x * blockDim.x + threadIdx.x;
    if (e < E) atomicAdd(&g_cur[ei[E + e]], 1);
}

__global__ void k_scan(int N) {
    __shared__ int s[1024];
    int t = threadIdx.x;
    int chunk = (N + 1023) / 1024;
    int b0 = t * chunk; if (b0 > N) b0 = N;
    int b1 = b0 + chunk; if (b1 > N) b1 = N;

    int sum = 0;
    for (int i = b0; i < b1; i++) sum += g_cur[i];
    s[t] = sum;
    __syncthreads();
    for (int off = 1; off < 1024; off <<= 1) {
        int v = (t >= off) ? s[t - off] : 0;
        __syncthreads();
        s[t] += v;
        __syncthreads();
    }
    int run = (t > 0) ? s[t - 1] : 0;
    for (int i = b0; i < b1; i++) {
        int c = g_cur[i];
        g_off[i] = run;
        g_cur[i] = run;
        run += c;
    }
    if (b0 < N && b1 == N) g_off[N] = run;
}

// Scatter: ONE 16B store per edge. {src, u, half2(ux,uy), uz}
__global__ void k_scatter(const int* __restrict__ ei,
                          const float* __restrict__ pos,
                          const float* __restrict__ pv,
                          int E) {
    int e = blockIdx.x * blockDim.x + threadIdx.x;
    if (e >= E) return;
    int s = ei[e];
    int d = ei[E + e];

    float dx = pos[d * 3 + 0] - pos[s * 3 + 0] + pv[e * 3 + 0];
    float dy = pos[d * 3 + 1] - pos[s * 3 + 1] + pv[e * 3 + 1];
    float dz = pos[d * 3 + 2] - pos[s * 3 + 2] + pv[e * 3 + 2];
    float len = sqrtf(dx * dx + dy * dy + dz * dz);
    float inv = 1.0f / (len + 1e-9f);
    float ux = dx * inv, uy = dy * inv, uz = dz * inv;

    float u = len * ((float)(NBINS - 1) / LMAX);
    u = fminf(fmaxf(u, 0.0f), (float)(NBINS - 1) - 0.001f);

    int p = atomicAdd(&g_cur[d], 1);

    __half2 hxy = __floats2half2_rn(ux, uy);
    float4 mt;
    mt.x = __int_as_float(s);
    mt.y = u;
    mt.z = __uint_as_float(*reinterpret_cast<unsigned*>(&hxy));
    mt.w = uz;
    g_meta[p] = mt;
}

// ---------------------------------------------------------------------------
// Per-layer node prologue, 4 nodes/warp. Layer 0 fuses node init.
//   hm = h @ Wmsg (stored fp16); agg = bconv + xattr@Wattr + h@Wself.
// ---------------------------------------------------------------------------
__global__ __launch_bounds__(256) void k_node_pre(const float* __restrict__ Wmsg,
                                                  const float* __restrict__ Wattr,
                                                  const float* __restrict__ Wself,
                                                  const float* __restrict__ bconv,
                                                  const int*   __restrict__ x,
                                                  const float* __restrict__ W_elem,
                                                  const float* __restrict__ W0,
                                                  const float* __restrict__ b0,
                                                  int layer, int N) {
    int w    = (blockIdx.x * blockDim.x + threadIdx.x) >> 5;
    int lane = threadIdx.x & 31;
    int n0 = w * 4;
    if (n0 >= N) return;

    const float* Wm = Wmsg  + layer * DIM * DIM;
    const float* Ws = Wself + layer * DIM * DIM;
    const float* Wa = Wattr + layer * DATTR * DIM;

    float h[4], xa[4];

    if (layer == 0) {
#pragma unroll
        for (int j = 0; j < 4; j++) {
            int n = n0 + j; if (n >= N) n = N - 1;
            int sp = x[n];
            xa[j] = (lane < DATTR) ? W_elem[sp * DATTR + lane] : 0.0f;
        }
        float bb = b0[lane];
#pragma unroll
        for (int j = 0; j < 4; j++) h[j] = bb;
#pragma unroll
        for (int kk = 0; kk < DATTR; kk++) {
            float w0k = W0[kk * DIM + lane];
#pragma unroll
            for (int j = 0; j < 4; j++) {
                float xj = __shfl_sync(0xffffffffu, xa[j], kk);
                h[j] = fmaf(xj, w0k, h[j]);
            }
        }
#pragma unroll
        for (int j = 0; j < 4; j++) {
            int n = n0 + j;
            if (n < N && lane < DATTR) g_xattr[n * DATTR + lane] = xa[j];
        }
    } else {
#pragma unroll
        for (int j = 0; j < 4; j++) {
            int n = n0 + j;
            h[j]  = (n < N) ? g_h[n * DIM + lane] : 0.0f;
            xa[j] = (n < N && lane < DATTR) ? g_xattr[n * DATTR + lane] : 0.0f;
        }
    }

    float bc = bconv[layer * DIM + lane];
    float hm[4] = {0.f, 0.f, 0.f, 0.f};
    float ag[4] = {bc, bc, bc, bc};

#pragma unroll
    for (int k = 0; k < DIM; k++) {
        float wm = Wm[k * DIM + lane];
        float ws = Ws[k * DIM + lane];
#pragma unroll
        for (int j = 0; j < 4; j++) {
            float hk = __shfl_sync(0xffffffffu, h[j], k);
            hm[j] = fmaf(hk, wm, hm[j]);
            ag[j] = fmaf(hk, ws, ag[j]);
        }
    }
#pragma unroll
    for (int kk = 0; kk < DATTR; kk++) {
        float wa = Wa[kk * DIM + lane];
#pragma unroll
        for (int j = 0; j < 4; j++) {
            float xj = __shfl_sync(0xffffffffu, xa[j], kk);
            ag[j] = fmaf(xj, wa, ag[j]);
        }
    }

#pragma unroll
    for (int j = 0; j < 4; j++) {
        int n = n0 + j;
        // pack hm channels (2*lane, 2*lane+1) into half2, lanes 0..15 store
        float a = __shfl_sync(0xffffffffu, hm[j], (2 * lane) & 31);
        float b = __shfl_sync(0xffffffffu, hm[j], (2 * lane + 1) & 31);
        if (n < N) {
            g_agg[n * DIM + lane] = ag[j];
            if (lane < 16)
                g_hmh[n * (DIM / 2) + lane] = __floats2half2_rn(a, b);
        }
    }
}

// ---------------------------------------------------------------------------
// Gather: warp per dst node; 4 edges in flight; 8-lane groups of 4 channels.
// Per edge: 16B meta (bcast), 16B table (L1), 8B fp16 hm row slice.
// ---------------------------------------------------------------------------
__global__ __launch_bounds__(256) void k_gather(const float* __restrict__ wsh,
                                                int layer, int N) {
    int w    = (blockIdx.x * blockDim.x + threadIdx.x) >> 5;
    int lane = threadIdx.x & 31;
    if (w >= N) return;
    int grp = lane >> 3;
    int sub = lane & 7;

    int beg = g_off[w];
    int end = g_off[w + 1];

    const uint4* __restrict__ T4 = (const uint4*)(g_Th + layer * NBINS * DIM);
    const uint2* __restrict__ HM = (const uint2*)g_hmh;

    float w0 = wsh[layer * 4 + 0], w1 = wsh[layer * 4 + 1];
    float w2 = wsh[layer * 4 + 2], w3 = wsh[layer * 4 + 3];

    float4 acc = make_float4(0.f, 0.f, 0.f, 0.f);

#pragma unroll 2
    for (int i = beg + grp; i < end; i += 4) {
        float4 mt = __ldg(&g_meta[i]);
        int    src = __float_as_int(mt.x);
        float  u   = mt.y;
        unsigned hb = __float_as_uint(mt.z);
        float2 uxy = __half22float2(*reinterpret_cast<__half2*>(&hb));
        float  shw = fmaf(w3, mt.w, fmaf(w2, uxy.y, fmaf(w1, uxy.x, w0)));

        int   b = (int)u;
        float f = u - (float)b;

        uint4 q  = __ldg(&T4[b * 8 + sub]);
        uint2 mh = __ldg(&HM[src * 8 + sub]);

        float2 c0 = __half22float2(*(const __half2*)&q.x);
        float2 c1 = __half22float2(*(const __half2*)&q.y);
        float2 c2 = __half22float2(*(const __half2*)&q.z);
        float2 c3 = __half22float2(*(const __half2*)&q.w);

        float2 m01 = __half22float2(*(const __half2*)&mh.x);
        float2 m23 = __half22float2(*(const __half2*)&mh.y);

        float r0 = fmaf(f, c0.y - c0.x, c0.x);
        float r1 = fmaf(f, c1.y - c1.x, c1.x);
        float r2 = fmaf(f, c2.y - c2.x, c2.x);
        float r3 = fmaf(f, c3.y - c3.x, c3.x);

        acc.x = fmaf(m01.x * r0, shw, acc.x);
        acc.y = fmaf(m01.y * r1, shw, acc.y);
        acc.z = fmaf(m23.x * r2, shw, acc.z);
        acc.w = fmaf(m23.y * r3, shw, acc.w);
    }

#pragma unroll
    for (int off = 8; off <= 16; off <<= 1) {
        acc.x += __shfl_xor_sync(0xffffffffu, acc.x, off);
        acc.y += __shfl_xor_sync(0xffffffffu, acc.y, off);
        acc.z += __shfl_xor_sync(0xffffffffu, acc.z, off);
        acc.w += __shfl_xor_sync(0xffffffffu, acc.w, off);
    }

    if (grp == 0) {
        float4 bse = ((const float4*)g_agg)[w * 8 + sub];
        float4 v;
        v.x = siluf(bse.x + acc.x);
        v.y = siluf(bse.y + acc.y);
        v.z = siluf(bse.z + acc.z);
        v.w = siluf(bse.w + acc.w);
        ((float4*)g_h)[w * 8 + sub] = v;
    }
}

// ---------------------------------------------------------------------------
__global__ void k_readout(const int* __restrict__ batch,
                          const float* __restrict__ Wp1,
                          const float* __restrict__ bp1,
                          const float* __restrict__ Wp2,
                          const float* __restrict__ bp2,
                          float* __restrict__ out,
                          int N) {
    int w    = (blockIdx.x * blockDim.x + threadIdx.x) >> 5;
    int lane = threadIdx.x & 31;
    if (w >= N) return;

    float h = g_h[w * DIM + lane];
    float p = (lane < 16) ? bp1[lane] : 0.0f;
#pragma unroll
    for (int k = 0; k < DIM; k++) {
        float hk = __shfl_sync(0xffffffffu, h, k);
        if (lane < 16) p += hk * Wp1[k * 16 + lane];
    }
    float y = 0.0f;
    if (lane < 16) {
        p = siluf(p);
        y = p * Wp2[lane];
    }
#pragma unroll
    for (int off = 16; off >= 1; off >>= 1)
        y += __shfl_xor_sync(0xffffffffu, y, off);

    if (lane == 0)
        atomicAdd(&out[batch[w]], SCALEC * (y + bp2[0]));
}

// ---------------------------------------------------------------------------
extern "C" void kernel_launch(void* const* d_in, const int* in_sizes, int n_in,
                              void* d_out, int out_size) {
    const int*   x      = (const int*)  d_in[0];
    const float* pos    = (const float*)d_in[1];
    const int*   ei     = (const int*)  d_in[2];
    const float* pv     = (const float*)d_in[3];
    const int*   batch  = (const int*)  d_in[4];
    const float* W_elem = (const float*)d_in[5];
    const float* W0     = (const float*)d_in[6];
    const float* b0     = (const float*)d_in[7];
    const float* Wr1    = (const float*)d_in[8];
    const float* br1    = (const float*)d_in[9];
    const float* Wr2    = (const float*)d_in[10];
    const float* Wmsg   = (const float*)d_in[11];
    const float* Wattr  = (const float*)d_in[12];
    const float* Wself  = (const float*)d_in[13];
    const float* bconv  = (const float*)d_in[14];
    const float* wsh    = (const float*)d_in[15];
    const float* Wp1    = (const float*)d_in[16];
    const float* bp1    = (const float*)d_in[17];
    const float* Wp2    = (const float*)d_in[18];
    const float* bp2    = (const float*)d_in[19];
    float*       out    = (float*)d_out;

    int N = in_sizes[0];
    int E = in_sizes[2] / 2;
    int G = out_size;
    if (N > NMAX) N = NMAX;
    if (E > EMAX) E = EMAX;

    const int TPB = 256;
    int nodeWarpBlocks  = (N * 32 + TPB - 1) / TPB;
    int node4WarpBlocks = (((N + 3) / 4) * 32 + TPB - 1) / TPB;
    int edgeThrBlocks   = (E + TPB - 1) / TPB;
    int edge4ThrBlocks  = ((E + 3) / 4 + TPB - 1) / TPB;
    int tableBlocks     = (3 * NBINS * 32 + TPB - 1) / TPB;

    void* curPtr = nullptr;
    cudaGetSymbolAddress(&curPtr, g_cur);
    cudaMemsetAsync(curPtr, 0, (size_t)N * sizeof(int), 0);

    k_table<<<tableBlocks, TPB>>>(Wr1, br1, Wr2);

    if ((E & 3) == 0) k_hist4<<<edge4ThrBlocks, TPB>>>(ei, E);
    else              k_hist1<<<edgeThrBlocks, TPB>>>(ei, E);
    k_scan   <<<1, 1024>>>(N);
    k_scatter<<<edgeThrBlocks, TPB>>>(ei, pos, pv, E);

    for (int i = 0; i < 3; i++) {
        k_node_pre<<<node4WarpBlocks, TPB>>>(Wmsg, Wattr, Wself, bconv,
                                             x, W_elem, W0, b0, i, N);
        k_gather  <<<nodeWarpBlocks, TPB>>>(wsh, i, N);
    }

    cudaMemsetAsync(out, 0, (size_t)G * sizeof(float), 0);   // SHIFT == 0
    k_readout<<<nodeWarpBlocks, TPB>>>(batch, Wp1, bp1, Wp2, bp2, out, N);
}

// round 9
// speedup vs baseline: 1.0005x; 1.0005x over previous
#include <cuda_runtime.h>
#include <cuda_fp16.h>
#include <math.h>
#include <stdint.h>

#define NMAX   50000
#define EMAX   1600000
#define DIM    32
#define DATTR  16
#define NRBF   8
#define NBINS  1024
#define LMAX   8.0f
#define RCUT   5.0f
#define SCALEC 1.0f

// ---------------- static device scratch ----------------
__device__ float   g_xattr[NMAX * DATTR];
__device__ float   g_h    [NMAX * DIM];
__device__ __half2 g_hmh  [NMAX * (DIM / 2)];   // hm rows in fp16 (64B/node)
__device__ float   g_agg  [NMAX * DIM];
__device__ __half2 g_Th   [3 * NBINS * DIM];    // packed (T[b], T[b+1]) endpoints
// CSR
__device__ int     g_off  [NMAX + 1];
__device__ int     g_cur  [NMAX];
__device__ float4  g_meta [EMAX];               // {src bits, u, half2(ux,uy) bits, uz}

static __device__ __forceinline__ float siluf(float v) {
    return v / (1.0f + __expf(-v));
}

// ---------------------------------------------------------------------------
// rw(len) for one table row (whole warp participates).
// ---------------------------------------------------------------------------
static __device__ __forceinline__ float eval_rw(const float* __restrict__ Wr1,
                                                const float* __restrict__ br1,
                                                const float* __restrict__ Wr2,
                                                int i, int b, int lane) {
    const float len   = (float)b * (LMAX / (float)(NBINS - 1));
    const float gamma = (NRBF / RCUT) * (NRBF / RCUT);

    float r = 0.0f;
    if (lane < NRBF) {
        float c = (float)lane * (RCUT / (float)(NRBF - 1));
        float d = len - c;
        r = expf(-gamma * d * d);
    }
    float t = br1[i * DIM + lane];
#pragma unroll
    for (int j = 0; j < NRBF; j++) {
        float rj = __shfl_sync(0xffffffffu, r, j);
        t += rj * Wr1[(i * NRBF + j) * DIM + lane];
    }
    t = fmaxf(t, 0.0f);

    float acc = 0.0f;
#pragma unroll
    for (int k = 0; k < DIM; k++) {
        float tk = __shfl_sync(0xffffffffu, t, k);
        acc += tk * Wr2[(i * DIM + k) * DIM + lane];
    }
    return acc;
}

__global__ void k_table(const float* __restrict__ Wr1,
                        const float* __restrict__ br1,
                        const float* __restrict__ Wr2) {
    int w    = (blockIdx.x * blockDim.x + threadIdx.x) >> 5;
    int lane = threadIdx.x & 31;
    if (w >= 3 * NBINS) return;
    int i = w / NBINS;
    int b = w - i * NBINS;
    int b1 = (b + 1 < NBINS) ? b + 1 : b;

    float a0 = eval_rw(Wr1, br1, Wr2, i, b,  lane);
    float a1 = eval_rw(Wr1, br1, Wr2, i, b1, lane);
    g_Th[(i * NBINS + b) * DIM + lane] = __floats2half2_rn(a0, a1);
}

// ---------------------------------------------------------------------------
// CSR build
// ---------------------------------------------------------------------------
__global__ void k_hist4(const int* __restrict__ ei, int E) {
    int e4 = (blockIdx.x * blockDim.x + threadIdx.x) * 4;
    if (e4 + 3 < E) {
        int4 v = *(const int4*)(ei + E + e4);
        atomicAdd(&g_cur[v.x], 1);
        atomicAdd(&g_cur[v.y], 1);
        atomicAdd(&g_cur[v.z], 1);
        atomicAdd(&g_cur[v.w], 1);
    } else {
        for (int e = e4; e < E; e++) atomicAdd(&g_cur[ei[E + e]], 1);
    }
}

__global__ void k_hist1(const int* __restrict__ ei, int E) {
    int e = blockIdx.x * blockDim.x + threadIdx.x;
    if (e < E) atomicAdd(&g_cur[ei[E + e]], 1);
}

__global__ void k_scan(int N) {
    __shared__ int s[1024];
    int t = threadIdx.x;
    int chunk = (N + 1023) / 1024;
    int b0 = t * chunk; if (b0 > N) b0 = N;
    int b1 = b0 + chunk; if (b1 > N) b1 = N;

    int sum = 0;
    for (int i = b0; i < b1; i++) sum += g_cur[i];
    s[t] = sum;
    __syncthreads();
    for (int off = 1; off < 1024; off <<= 1) {
        int v = (t >= off) ? s[t - off] : 0;
        __syncthreads();
        s[t] += v;
        __syncthreads();
    }
    int run = (t > 0) ? s[t - 1] : 0;
    for (int i = b0; i < b1; i++) {
        int c = g_cur[i];
        g_off[i] = run;
        g_cur[i] = run;
        run += c;
    }
    if (b0 < N && b1 == N) g_off[N] = run;
}

// Scatter: ONE 16B store per edge. {src, u, half2(ux,uy), uz}
__global__ void k_scatter(const int* __restrict__ ei,
                          const float* __restrict__ pos,
                          const float* __restrict__ pv,
                          int E) {
    int e = blockIdx.x * blockDim.x + threadIdx.x;
    if (e >= E) return;
    int s = ei[e];
    int d = ei[E + e];

    float dx = pos[d * 3 + 0] - pos[s * 3 + 0] + pv[e * 3 + 0];
    float dy = pos[d * 3 + 1] - pos[s * 3 + 1] + pv[e * 3 + 1];
    float dz = pos[d * 3 + 2] - pos[s * 3 + 2] + pv[e * 3 + 2];
    float len = sqrtf(dx * dx + dy * dy + dz * dz);
    float inv = 1.0f / (len + 1e-9f);
    float ux = dx * inv, uy = dy * inv, uz = dz * inv;

    float u = len * ((float)(NBINS - 1) / LMAX);
    u = fminf(fmaxf(u, 0.0f), (float)(NBINS - 1) - 0.001f);

    int p = atomicAdd(&g_cur[d], 1);

    __half2 hxy = __floats2half2_rn(ux, uy);
    float4 mt;
    mt.x = __int_as_float(s);
    mt.y = u;
    mt.z = __uint_as_float(*reinterpret_cast<unsigned*>(&hxy));
    mt.w = uz;
    g_meta[p] = mt;
}

// ---------------------------------------------------------------------------
// Per-layer node prologue, 4 nodes/warp. Layer 0 fuses node init.
//   hm = h @ Wmsg (stored fp16); agg = bconv + xattr@Wattr + h@Wself.
// ---------------------------------------------------------------------------
__global__ __launch_bounds__(256) void k_node_pre(const float* __restrict__ Wmsg,
                                                  const float* __restrict__ Wattr,
                                                  const float* __restrict__ Wself,
                                                  const float* __restrict__ bconv,
                                                  const int*   __restrict__ x,
                                                  const float* __restrict__ W_elem,
                                                  const float* __restrict__ W0,
                                                  const float* __restrict__ b0,
                                                  int layer, int N) {
    int w    = (blockIdx.x * blockDim.x + threadIdx.x) >> 5;
    int lane = threadIdx.x & 31;
    int n0 = w * 4;
    if (n0 >= N) return;

    const float* Wm = Wmsg  + layer * DIM * DIM;
    const float* Ws = Wself + layer * DIM * DIM;
    const float* Wa = Wattr + layer * DATTR * DIM;

    float h[4], xa[4];

    if (layer == 0) {
#pragma unroll
        for (int j = 0; j < 4; j++) {
            int n = n0 + j; if (n >= N) n = N - 1;
            int sp = x[n];
            xa[j] = (lane < DATTR) ? W_elem[sp * DATTR + lane] : 0.0f;
        }
        float bb = b0[lane];
#pragma unroll
        for (int j = 0; j < 4; j++) h[j] = bb;
#pragma unroll
        for (int kk = 0; kk < DATTR; kk++) {
            float w0k = W0[kk * DIM + lane];
#pragma unroll
            for (int j = 0; j < 4; j++) {
                float xj = __shfl_sync(0xffffffffu, xa[j], kk);
                h[j] = fmaf(xj, w0k, h[j]);
            }
        }
#pragma unroll
        for (int j = 0; j < 4; j++) {
            int n = n0 + j;
            if (n < N && lane < DATTR) g_xattr[n * DATTR + lane] = xa[j];
        }
    } else {
#pragma unroll
        for (int j = 0; j < 4; j++) {
            int n = n0 + j;
            h[j]  = (n < N) ? g_h[n * DIM + lane] : 0.0f;
            xa[j] = (n < N && lane < DATTR) ? g_xattr[n * DATTR + lane] : 0.0f;
        }
    }

    float bc = bconv[layer * DIM + lane];
    float hm[4] = {0.f, 0.f, 0.f, 0.f};
    float ag[4] = {bc, bc, bc, bc};

#pragma unroll
    for (int k = 0; k < DIM; k++) {
        float wm = Wm[k * DIM + lane];
        float ws = Ws[k * DIM + lane];
#pragma unroll
        for (int j = 0; j < 4; j++) {
            float hk = __shfl_sync(0xffffffffu, h[j], k);
            hm[j] = fmaf(hk, wm, hm[j]);
            ag[j] = fmaf(hk, ws, ag[j]);
        }
    }
#pragma unroll
    for (int kk = 0; kk < DATTR; kk++) {
        float wa = Wa[kk * DIM + lane];
#pragma unroll
        for (int j = 0; j < 4; j++) {
            float xj = __shfl_sync(0xffffffffu, xa[j], kk);
            ag[j] = fmaf(xj, wa, ag[j]);
        }
    }

#pragma unroll
    for (int j = 0; j < 4; j++) {
        int n = n0 + j;
        // pack hm channels (2*lane, 2*lane+1) into half2, lanes 0..15 store
        float a = __shfl_sync(0xffffffffu, hm[j], (2 * lane) & 31);
        float b = __shfl_sync(0xffffffffu, hm[j], (2 * lane + 1) & 31);
        if (n < N) {
            g_agg[n * DIM + lane] = ag[j];
            if (lane < 16)
                g_hmh[n * (DIM / 2) + lane] = __floats2half2_rn(a, b);
        }
    }
}

// ---------------------------------------------------------------------------
// Gather: warp per dst node; 4 edges in flight; 8-lane groups of 4 channels.
// Per edge: 16B meta (bcast), 16B table (L1), 8B fp16 hm row slice.
// ---------------------------------------------------------------------------
__global__ __launch_bounds__(256) void k_gather(const float* __restrict__ wsh,
                                                int layer, int N) {
    int w    = (blockIdx.x * blockDim.x + threadIdx.x) >> 5;
    int lane = threadIdx.x & 31;
    if (w >= N) return;
    int grp = lane >> 3;
    int sub = lane & 7;

    int beg = g_off[w];
    int end = g_off[w + 1];

    const uint4* __restrict__ T4 = (const uint4*)(g_Th + layer * NBINS * DIM);
    const uint2* __restrict__ HM = (const uint2*)g_hmh;

    float w0 = wsh[layer * 4 + 0], w1 = wsh[layer * 4 + 1];
    float w2 = wsh[layer * 4 + 2], w3 = wsh[layer * 4 + 3];

    float4 acc = make_float4(0.f, 0.f, 0.f, 0.f);

#pragma unroll 2
    for (int i = beg + grp; i < end; i += 4) {
        float4 mt = __ldg(&g_meta[i]);
        int    src = __float_as_int(mt.x);
        float  u   = mt.y;
        unsigned hb = __float_as_uint(mt.z);
        float2 uxy = __half22float2(*reinterpret_cast<__half2*>(&hb));
        float  shw = fmaf(w3, mt.w, fmaf(w2, uxy.y, fmaf(w1, uxy.x, w0)));

        int   b = (int)u;
        float f = u - (float)b;

        uint4 q  = __ldg(&T4[b * 8 + sub]);
        uint2 mh = __ldg(&HM[src * 8 + sub]);

        float2 c0 = __half22float2(*(const __half2*)&q.x);
        float2 c1 = __half22float2(*(const __half2*)&q.y);
        float2 c2 = __half22float2(*(const __half2*)&q.z);
        float2 c3 = __half22float2(*(const __half2*)&q.w);

        float2 m01 = __half22float2(*(const __half2*)&mh.x);
        float2 m23 = __half22float2(*(const __half2*)&mh.y);

        float r0 = fmaf(f, c0.y - c0.x, c0.x);
        float r1 = fmaf(f, c1.y - c1.x, c1.x);
        float r2 = fmaf(f, c2.y - c2.x, c2.x);
        float r3 = fmaf(f, c3.y - c3.x, c3.x);

        acc.x = fmaf(m01.x * r0, shw, acc.x);
        acc.y = fmaf(m01.y * r1, shw, acc.y);
        acc.z = fmaf(m23.x * r2, shw, acc.z);
        acc.w = fmaf(m23.y * r3, shw, acc.w);
    }

#pragma unroll
    for (int off = 8; off <= 16; off <<= 1) {
        acc.x += __shfl_xor_sync(0xffffffffu, acc.x, off);
        acc.y += __shfl_xor_sync(0xffffffffu, acc.y, off);
        acc.z += __shfl_xor_sync(0xffffffffu, acc.z, off);
        acc.w += __shfl_xor_sync(0xffffffffu, acc.w, off);
    }

    if (grp == 0) {
        float4 bse = ((const float4*)g_agg)[w * 8 + sub];
        float4 v;
        v.x = siluf(bse.x + acc.x);
        v.y = siluf(bse.y + acc.y);
        v.z = siluf(bse.z + acc.z);
        v.w = siluf(bse.w + acc.w);
        ((float4*)g_h)[w * 8 + sub] = v;
    }
}

// ---------------------------------------------------------------------------
__global__ void k_readout(const int* __restrict__ batch,
                          const float* __restrict__ Wp1,
                          const float* __restrict__ bp1,
                          const float* __restrict__ Wp2,
                          const float* __restrict__ bp2,
                          float* __restrict__ out,
                          int N) {
    int w    = (blockIdx.x * blockDim.x + threadIdx.x) >> 5;
    int lane = threadIdx.x & 31;
    if (w >= N) return;

    float h = g_h[w * DIM + lane];
    float p = (lane < 16) ? bp1[lane] : 0.0f;
#pragma unroll
    for (int k = 0; k < DIM; k++) {
        float hk = __shfl_sync(0xffffffffu, h, k);
        if (lane < 16) p += hk * Wp1[k * 16 + lane];
    }
    float y = 0.0f;
    if (lane < 16) {
        p = siluf(p);
        y = p * Wp2[lane];
    }
#pragma unroll
    for (int off = 16; off >= 1; off >>= 1)
        y += __shfl_xor_sync(0xffffffffu, y, off);

    if (lane == 0)
        atomicAdd(&out[batch[w]], SCALEC * (y + bp2[0]));
}

// ---------------------------------------------------------------------------
extern "C" void kernel_launch(void* const* d_in, const int* in_sizes, int n_in,
                              void* d_out, int out_size) {
    const int*   x      = (const int*)  d_in[0];
    const float* pos    = (const float*)d_in[1];
    const int*   ei     = (const int*)  d_in[2];
    const float* pv     = (const float*)d_in[3];
    const int*   batch  = (const int*)  d_in[4];
    const float* W_elem = (const float*)d_in[5];
    const float* W0     = (const float*)d_in[6];
    const float* b0     = (const float*)d_in[7];
    const float* Wr1    = (const float*)d_in[8];
    const float* br1    = (const float*)d_in[9];
    const float* Wr2    = (const float*)d_in[10];
    const float* Wmsg   = (const float*)d_in[11];
    const float* Wattr  = (const float*)d_in[12];
    const float* Wself  = (const float*)d_in[13];
    const float* bconv  = (const float*)d_in[14];
    const float* wsh    = (const float*)d_in[15];
    const float* Wp1    = (const float*)d_in[16];
    const float* bp1    = (const float*)d_in[17];
    const float* Wp2    = (const float*)d_in[18];
    const float* bp2    = (const float*)d_in[19];
    float*       out    = (float*)d_out;

    int N = in_sizes[0];
    int E = in_sizes[2] / 2;
    int G = out_size;
    if (N > NMAX) N = NMAX;
    if (E > EMAX) E = EMAX;

    const int TPB = 256;
    int nodeWarpBlocks  = (N * 32 + TPB - 1) / TPB;
    int node4WarpBlocks = (((N + 3) / 4) * 32 + TPB - 1) / TPB;
    int edgeThrBlocks   = (E + TPB - 1) / TPB;
    int edge4ThrBlocks  = ((E + 3) / 4 + TPB - 1) / TPB;
    int tableBlocks     = (3 * NBINS * 32 + TPB - 1) / TPB;

    void* curPtr = nullptr;
    cudaGetSymbolAddress(&curPtr, g_cur);
    cudaMemsetAsync(curPtr, 0, (size_t)N * sizeof(int), 0);

    k_table<<<tableBlocks, TPB>>>(Wr1, br1, Wr2);

    if ((E & 3) == 0) k_hist4<<<edge4ThrBlocks, TPB>>>(ei, E);
    else              k_hist1<<<edgeThrBlocks, TPB>>>(ei, E);
    k_scan   <<<1, 1024>>>(N);
    k_scatter<<<edgeThrBlocks, TPB>>>(ei, pos, pv, E);

    for (int i = 0; i < 3; i++) {
        k_node_pre<<<node4WarpBlocks, TPB>>>(Wmsg, Wattr, Wself, bconv,
                                             x, W_elem, W0, b0, i, N);
        k_gather  <<<nodeWarpBlocks, TPB>>>(wsh, i, N);
    }

    cudaMemsetAsync(out, 0, (size_t)G * sizeof(float), 0);   // SHIFT == 0
    k_readout<<<nodeWarpBlocks, TPB>>>(batch, Wp1, bp1, Wp2, bp2, out, N);
}

// round 10
// speedup vs baseline: 1.0127x; 1.0123x over previous
#include <cuda_runtime.h>
#include <cuda_fp16.h>
#include <math.h>
#include <stdint.h>

#define NMAX   50000
#define EMAX   1600000
#define DIM    32
#define DATTR  16
#define NRBF   8
#define NBINS  1024
#define LMAX   8.0f
#define RCUT   5.0f
#define SCALEC 1.0f

// ---------------- static device scratch ----------------
__device__ float   g_xattr[NMAX * DATTR];
__device__ float   g_h    [NMAX * DIM];
__device__ __half2 g_hmh  [NMAX * (DIM / 2)];   // hm rows in fp16 (64B/node)
__device__ float   g_agg  [NMAX * DIM];
__device__ __half2 g_Th   [3 * NBINS * DIM];    // packed (T[b], T[b+1]) endpoints
// CSR
__device__ int     g_off  [NMAX + 1];
__device__ int     g_cur  [NMAX];
__device__ float4  g_meta [EMAX];               // {src bits, u, half2(ux,uy) bits, uz}

static __device__ __forceinline__ float siluf(float v) {
    return v / (1.0f + __expf(-v));
}

// ---------------------------------------------------------------------------
// rw(len) for one table row (whole warp participates).
// ---------------------------------------------------------------------------
static __device__ __forceinline__ float eval_rw(const float* __restrict__ Wr1,
                                                const float* __restrict__ br1,
                                                const float* __restrict__ Wr2,
                                                int i, int b, int lane) {
    const float len   = (float)b * (LMAX / (float)(NBINS - 1));
    const float gamma = (NRBF / RCUT) * (NRBF / RCUT);

    float r = 0.0f;
    if (lane < NRBF) {
        float c = (float)lane * (RCUT / (float)(NRBF - 1));
        float d = len - c;
        r = expf(-gamma * d * d);
    }
    float t = br1[i * DIM + lane];
#pragma unroll
    for (int j = 0; j < NRBF; j++) {
        float rj = __shfl_sync(0xffffffffu, r, j);
        t += rj * Wr1[(i * NRBF + j) * DIM + lane];
    }
    t = fmaxf(t, 0.0f);

    float acc = 0.0f;
#pragma unroll
    for (int k = 0; k < DIM; k++) {
        float tk = __shfl_sync(0xffffffffu, t, k);
        acc += tk * Wr2[(i * DIM + k) * DIM + lane];
    }
    return acc;
}

__global__ void k_table(const float* __restrict__ Wr1,
                        const float* __restrict__ br1,
                        const float* __restrict__ Wr2) {
    int w    = (blockIdx.x * blockDim.x + threadIdx.x) >> 5;
    int lane = threadIdx.x & 31;
    if (w >= 3 * NBINS) return;
    int i = w / NBINS;
    int b = w - i * NBINS;
    int b1 = (b + 1 < NBINS) ? b + 1 : b;

    float a0 = eval_rw(Wr1, br1, Wr2, i, b,  lane);
    float a1 = eval_rw(Wr1, br1, Wr2, i, b1, lane);
    g_Th[(i * NBINS + b) * DIM + lane] = __floats2half2_rn(a0, a1);
}

// ---------------------------------------------------------------------------
// CSR build
// ---------------------------------------------------------------------------
__global__ void k_hist4(const int* __restrict__ ei, int E) {
    int e4 = (blockIdx.x * blockDim.x + threadIdx.x) * 4;
    if (e4 + 3 < E) {
        int4 v = *(const int4*)(ei + E + e4);
        atomicAdd(&g_cur[v.x], 1);
        atomicAdd(&g_cur[v.y], 1);
        atomicAdd(&g_cur[v.z], 1);
        atomicAdd(&g_cur[v.w], 1);
    } else {
        for (int e = e4; e < E; e++) atomicAdd(&g_cur[ei[E + e]], 1);
    }
}

__global__ void k_hist1(const int* __restrict__ ei, int E) {
    int e = blockIdx.x * blockDim.x + threadIdx.x;
    if (e < E) atomicAdd(&g_cur[ei[E + e]], 1);
}

__global__ void k_scan(int N) {
    __shared__ int s[1024];
    int t = threadIdx.x;
    int chunk = (N + 1023) / 1024;
    int b0 = t * chunk; if (b0 > N) b0 = N;
    int b1 = b0 + chunk; if (b1 > N) b1 = N;

    int sum = 0;
    for (int i = b0; i < b1; i++) sum += g_cur[i];
    s[t] = sum;
    __syncthreads();
    for (int off = 1; off < 1024; off <<= 1) {
        int v = (t >= off) ? s[t - off] : 0;
        __syncthreads();
        s[t] += v;
        __syncthreads();
    }
    int run = (t > 0) ? s[t - 1] : 0;
    for (int i = b0; i < b1; i++) {
        int c = g_cur[i];
        g_off[i] = run;
        g_cur[i] = run;
        run += c;
    }
    if (b0 < N && b1 == N) g_off[N] = run;
}

// Scatter: ONE 16B store per edge. {src, u, half2(ux,uy), uz}
__global__ void k_scatter(const int* __restrict__ ei,
                          const float* __restrict__ pos,
                          const float* __restrict__ pv,
                          int E) {
    int e = blockIdx.x * blockDim.x + threadIdx.x;
    if (e >= E) return;
    int s = ei[e];
    int d = ei[E + e];

    float dx = pos[d * 3 + 0] - pos[s * 3 + 0] + pv[e * 3 + 0];
    float dy = pos[d * 3 + 1] - pos[s * 3 + 1] + pv[e * 3 + 1];
    float dz = pos[d * 3 + 2] - pos[s * 3 + 2] + pv[e * 3 + 2];
    float len = sqrtf(dx * dx + dy * dy + dz * dz);
    float inv = 1.0f / (len + 1e-9f);
    float ux = dx * inv, uy = dy * inv, uz = dz * inv;

    float u = len * ((float)(NBINS - 1) / LMAX);
    u = fminf(fmaxf(u, 0.0f), (float)(NBINS - 1) - 0.001f);

    int p = atomicAdd(&g_cur[d], 1);

    __half2 hxy = __floats2half2_rn(ux, uy);
    float4 mt;
    mt.x = __int_as_float(s);
    mt.y = u;
    mt.z = __uint_as_float(*reinterpret_cast<unsigned*>(&hxy));
    mt.w = uz;
    g_meta[p] = mt;
}

// ---------------------------------------------------------------------------
// Per-layer node prologue, 4 nodes/warp. Layer 0 fuses node init.
//   hm = h @ Wmsg (stored fp16); agg = bconv + xattr@Wattr + h@Wself.
// ---------------------------------------------------------------------------
__global__ __launch_bounds__(256) void k_node_pre(const float* __restrict__ Wmsg,
                                                  const float* __restrict__ Wattr,
                                                  const float* __restrict__ Wself,
                                                  const float* __restrict__ bconv,
                                                  const int*   __restrict__ x,
                                                  const float* __restrict__ W_elem,
                                                  const float* __restrict__ W0,
                                                  const float* __restrict__ b0,
                                                  int layer, int N) {
    int w    = (blockIdx.x * blockDim.x + threadIdx.x) >> 5;
    int lane = threadIdx.x & 31;
    int n0 = w * 4;
    if (n0 >= N) return;

    const float* Wm = Wmsg  + layer * DIM * DIM;
    const float* Ws = Wself + layer * DIM * DIM;
    const float* Wa = Wattr + layer * DATTR * DIM;

    float h[4], xa[4];

    if (layer == 0) {
#pragma unroll
        for (int j = 0; j < 4; j++) {
            int n = n0 + j; if (n >= N) n = N - 1;
            int sp = x[n];
            xa[j] = (lane < DATTR) ? W_elem[sp * DATTR + lane] : 0.0f;
        }
        float bb = b0[lane];
#pragma unroll
        for (int j = 0; j < 4; j++) h[j] = bb;
#pragma unroll
        for (int kk = 0; kk < DATTR; kk++) {
            float w0k = W0[kk * DIM + lane];
#pragma unroll
            for (int j = 0; j < 4; j++) {
                float xj = __shfl_sync(0xffffffffu, xa[j], kk);
                h[j] = fmaf(xj, w0k, h[j]);
            }
        }
#pragma unroll
        for (int j = 0; j < 4; j++) {
            int n = n0 + j;
            if (n < N && lane < DATTR) g_xattr[n * DATTR + lane] = xa[j];
        }
    } else {
#pragma unroll
        for (int j = 0; j < 4; j++) {
            int n = n0 + j;
            h[j]  = (n < N) ? g_h[n * DIM + lane] : 0.0f;
            xa[j] = (n < N && lane < DATTR) ? g_xattr[n * DATTR + lane] : 0.0f;
        }
    }

    float bc = bconv[layer * DIM + lane];
    float hm[4] = {0.f, 0.f, 0.f, 0.f};
    float ag[4] = {bc, bc, bc, bc};

#pragma unroll
    for (int k = 0; k < DIM; k++) {
        float wm = Wm[k * DIM + lane];
        float ws = Ws[k * DIM + lane];
#pragma unroll
        for (int j = 0; j < 4; j++) {
            float hk = __shfl_sync(0xffffffffu, h[j], k);
            hm[j] = fmaf(hk, wm, hm[j]);
            ag[j] = fmaf(hk, ws, ag[j]);
        }
    }
#pragma unroll
    for (int kk = 0; kk < DATTR; kk++) {
        float wa = Wa[kk * DIM + lane];
#pragma unroll
        for (int j = 0; j < 4; j++) {
            float xj = __shfl_sync(0xffffffffu, xa[j], kk);
            ag[j] = fmaf(xj, wa, ag[j]);
        }
    }

#pragma unroll
    for (int j = 0; j < 4; j++) {
        int n = n0 + j;
        // pack hm channels (2*lane, 2*lane+1) into half2, lanes 0..15 store
        float a = __shfl_sync(0xffffffffu, hm[j], (2 * lane) & 31);
        float b = __shfl_sync(0xffffffffu, hm[j], (2 * lane + 1) & 31);
        if (n < N) {
            g_agg[n * DIM + lane] = ag[j];
            if (lane < 16)
                g_hmh[n * (DIM / 2) + lane] = __floats2half2_rn(a, b);
        }
    }
}

// ---------------------------------------------------------------------------
// Gather: warp per dst node; 4 edges in flight; 8-lane groups of 4 channels.
// Per edge: 16B meta (bcast), 16B table (L1), 8B fp16 hm row slice.
// ---------------------------------------------------------------------------
__global__ __launch_bounds__(256) void k_gather(const float* __restrict__ wsh,
                                                int layer, int N) {
    int w    = (blockIdx.x * blockDim.x + threadIdx.x) >> 5;
    int lane = threadIdx.x & 31;
    if (w >= N) return;
    int grp = lane >> 3;
    int sub = lane & 7;

    int beg = g_off[w];
    int end = g_off[w + 1];

    const uint4* __restrict__ T4 = (const uint4*)(g_Th + layer * NBINS * DIM);
    const uint2* __restrict__ HM = (const uint2*)g_hmh;

    float w0 = wsh[layer * 4 + 0], w1 = wsh[layer * 4 + 1];
    float w2 = wsh[layer * 4 + 2], w3 = wsh[layer * 4 + 3];

    float4 acc = make_float4(0.f, 0.f, 0.f, 0.f);

#pragma unroll 2
    for (int i = beg + grp; i < end; i += 4) {
        float4 mt = __ldg(&g_meta[i]);
        int    src = __float_as_int(mt.x);
        float  u   = mt.y;
        unsigned hb = __float_as_uint(mt.z);
        float2 uxy = __half22float2(*reinterpret_cast<__half2*>(&hb));
        float  shw = fmaf(w3, mt.w, fmaf(w2, uxy.y, fmaf(w1, uxy.x, w0)));

        int   b = (int)u;
        float f = u - (float)b;

        uint4 q  = __ldg(&T4[b * 8 + sub]);
        uint2 mh = __ldg(&HM[src * 8 + sub]);

        float2 c0 = __half22float2(*(const __half2*)&q.x);
        float2 c1 = __half22float2(*(const __half2*)&q.y);
        float2 c2 = __half22float2(*(const __half2*)&q.z);
        float2 c3 = __half22float2(*(const __half2*)&q.w);

        float2 m01 = __half22float2(*(const __half2*)&mh.x);
        float2 m23 = __half22float2(*(const __half2*)&mh.y);

        float r0 = fmaf(f, c0.y - c0.x, c0.x);
        float r1 = fmaf(f, c1.y - c1.x, c1.x);
        float r2 = fmaf(f, c2.y - c2.x, c2.x);
        float r3 = fmaf(f, c3.y - c3.x, c3.x);

        acc.x = fmaf(m01.x * r0, shw, acc.x);
        acc.y = fmaf(m01.y * r1, shw, acc.y);
        acc.z = fmaf(m23.x * r2, shw, acc.z);
        acc.w = fmaf(m23.y * r3, shw, acc.w);
    }

#pragma unroll
    for (int off = 8; off <= 16; off <<= 1) {
        acc.x += __shfl_xor_sync(0xffffffffu, acc.x, off);
        acc.y += __shfl_xor_sync(0xffffffffu, acc.y, off);
        acc.z += __shfl_xor_sync(0xffffffffu, acc.z, off);
        acc.w += __shfl_xor_sync(0xffffffffu, acc.w, off);
    }

    if (grp == 0) {
        float4 bse = ((const float4*)g_agg)[w * 8 + sub];
        float4 v;
        v.x = siluf(bse.x + acc.x);
        v.y = siluf(bse.y + acc.y);
        v.z = siluf(bse.z + acc.z);
        v.w = siluf(bse.w + acc.w);
        ((float4*)g_h)[w * 8 + sub] = v;
    }
}

// ---------------------------------------------------------------------------
__global__ void k_readout(const int* __restrict__ batch,
                          const float* __restrict__ Wp1,
                          const float* __restrict__ bp1,
                          const float* __restrict__ Wp2,
                          const float* __restrict__ bp2,
                          float* __restrict__ out,
                          int N) {
    int w    = (blockIdx.x * blockDim.x + threadIdx.x) >> 5;
    int lane = threadIdx.x & 31;
    if (w >= N) return;

    float h = g_h[w * DIM + lane];
    float p = (lane < 16) ? bp1[lane] : 0.0f;
#pragma unroll
    for (int k = 0; k < DIM; k++) {
        float hk = __shfl_sync(0xffffffffu, h, k);
        if (lane < 16) p += hk * Wp1[k * 16 + lane];
    }
    float y = 0.0f;
    if (lane < 16) {
        p = siluf(p);
        y = p * Wp2[lane];
    }
#pragma unroll
    for (int off = 16; off >= 1; off >>= 1)
        y += __shfl_xor_sync(0xffffffffu, y, off);

    if (lane == 0)
        atomicAdd(&out[batch[w]], SCALEC * (y + bp2[0]));
}

// ---------------------------------------------------------------------------
extern "C" void kernel_launch(void* const* d_in, const int* in_sizes, int n_in,
                              void* d_out, int out_size) {
    const int*   x      = (const int*)  d_in[0];
    const float* pos    = (const float*)d_in[1];
    const int*   ei     = (const int*)  d_in[2];
    const float* pv     = (const float*)d_in[3];
    const int*   batch  = (const int*)  d_in[4];
    const float* W_elem = (const float*)d_in[5];
    const float* W0     = (const float*)d_in[6];
    const float* b0     = (const float*)d_in[7];
    const float* Wr1    = (const float*)d_in[8];
    const float* br1    = (const float*)d_in[9];
    const float* Wr2    = (const float*)d_in[10];
    const float* Wmsg   = (const float*)d_in[11];
    const float* Wattr  = (const float*)d_in[12];
    const float* Wself  = (const float*)d_in[13];
    const float* bconv  = (const float*)d_in[14];
    const float* wsh    = (const float*)d_in[15];
    const float* Wp1    = (const float*)d_in[16];
    const float* bp1    = (const float*)d_in[17];
    const float* Wp2    = (const float*)d_in[18];
    const float* bp2    = (const float*)d_in[19];
    float*       out    = (float*)d_out;

    int N = in_sizes[0];
    int E = in_sizes[2] / 2;
    int G = out_size;
    if (N > NMAX) N = NMAX;
    if (E > EMAX) E = EMAX;

    const int TPB = 256;
    int nodeWarpBlocks  = (N * 32 + TPB - 1) / TPB;
    int node4WarpBlocks = (((N + 3) / 4) * 32 + TPB - 1) / TPB;
    int edgeThrBlocks   = (E + TPB - 1) / TPB;
    int edge4ThrBlocks  = ((E + 3) / 4 + TPB - 1) / TPB;
    int tableBlocks     = (3 * NBINS * 32 + TPB - 1) / TPB;

    void* curPtr = nullptr;
    cudaGetSymbolAddress(&curPtr, g_cur);
    cudaMemsetAsync(curPtr, 0, (size_t)N * sizeof(int), 0);

    k_table<<<tableBlocks, TPB>>>(Wr1, br1, Wr2);

    if ((E & 3) == 0) k_hist4<<<edge4ThrBlocks, TPB>>>(ei, E);
    else              k_hist1<<<edgeThrBlocks, TPB>>>(ei, E);
    k_scan   <<<1, 1024>>>(N);
    k_scatter<<<edgeThrBlocks, TPB>>>(ei, pos, pv, E);

    for (int i = 0; i < 3; i++) {
        k_node_pre<<<node4WarpBlocks, TPB>>>(Wmsg, Wattr, Wself, bconv,
                                             x, W_elem, W0, b0, i, N);
        k_gather  <<<nodeWarpBlocks, TPB>>>(wsh, i, N);
    }

    cudaMemsetAsync(out, 0, (size_t)G * sizeof(float), 0);   // SHIFT == 0
    k_readout<<<nodeWarpBlocks, TPB>>>(batch, Wp1, bp1, Wp2, bp2, out, N);
}